// round 3
// baseline (speedup 1.0000x reference)
#include <cuda_runtime.h>
#include <cuda_bf16.h>
#include <cstdint>

// Problem shape (fixed for this problem id)
#define BB   16
#define SS   768
#define DE   16
#define HID  128
#define BSN  (BB*SS)          // 12288 rows
#define ROWF (SS*DE)          // 12288 floats per (b,i) row
#define ROWF4 (ROWF/4)        // 3072 float4 per row
#define IMP_BLOCKS (BSN/8)    // 1536 blocks in imp kernel

// ---- scratch (no allocations allowed) ----
__device__ float g_edge_sum[BSN];
__device__ float g_dist[BSN];
__device__ float g_imp[BSN];
__device__ float g_wnc[HID];
__device__ float g_v[64];
__device__ float g_C[1];
__device__ float g_maskf[BSN];           // 0.0 = pocket, +inf = not
__device__ unsigned char g_mask[BSN];
__device__ unsigned int g_arrive;

// ============================================================================
// Kernel 1: prep — detect pocket_mask dtype, canonicalize, fold weights,
// reset arrival counter.
// ============================================================================
__global__ void prep_kernel(const void* __restrict__ pocket_raw,
                            const float* __restrict__ W_node,
                            const float* __restrict__ b_node,
                            const float* __restrict__ W_e2,
                            const float* __restrict__ b_e2,
                            const float* __restrict__ W_imp,
                            const float* __restrict__ b_imp)
{
    __shared__ int s_fone, s_other;
    const int t = threadIdx.x;
    if (t == 0) { s_fone = 0; s_other = 0; g_arrive = 0u; }
    __syncthreads();

    // Scan only the first BSN bytes (= BSN/4 words) — safe for bool/int/float.
    const unsigned int* w = (const unsigned int*)pocket_raw;
    int lf = 0, lo = 0;
    for (int k = t; k < BSN / 4; k += 256) {
        unsigned int x = w[k];
        if (x == 0x3F800000u) lf++;
        else if (x != 0u && x != 1u) lo++;
    }
    if (lf) atomicAdd(&s_fone, lf);
    if (lo) atomicAdd(&s_other, lo);
    __syncthreads();
    // mode: 0=float32 (saw 1.0f words), 2=bool/u8 (saw packed-byte patterns), 1=int32
    const int mode = (s_fone > 0) ? 0 : ((s_other > 0) ? 2 : 1);

    const float INF = __int_as_float(0x7f800000);
    for (int idx = t; idx < BSN; idx += 256) {
        bool m;
        if (mode == 0)      m = ((const float*)pocket_raw)[idx] != 0.0f;
        else if (mode == 1) m = ((const int*)pocket_raw)[idx] != 0;
        else                m = ((const unsigned char*)pocket_raw)[idx] != 0;
        g_mask[idx]  = m ? 1 : 0;
        g_maskf[idx] = m ? 0.0f : INF;
    }

    if (t < HID) {
        float s = 0.0f;
        #pragma unroll
        for (int k = 0; k < 32; k++) s += W_node[t * 32 + k] * W_imp[k];
        g_wnc[t] = s;
    }
    if (t < 64) {
        float s = 0.0f;
        #pragma unroll
        for (int k = 0; k < 32; k++) s += W_e2[t * 32 + k] * W_imp[32 + k];
        g_v[t] = s;
    }
    if (t == 0) {
        float c = b_imp[0];
        #pragma unroll
        for (int k = 0; k < 32; k++) c += b_node[k] * W_imp[k];
        #pragma unroll
        for (int k = 0; k < 32; k++) c += b_e2[k] * W_imp[32 + k];
        g_C[0] = c;
    }
}

// ============================================================================
// Kernel 2: edge pass — the 604 MB streaming pass.
// TWO rows per block (same batch => shared mask; doubled per-thread MLP).
// Streaming loads (__ldcs): each byte touched exactly once.
// Channel-0 element: float4 index k with k%4==0, component .x, j = k>>2.
// Min via additive-inf mask: cand = v.x + maskf[j].
// ============================================================================
__global__ void __launch_bounds__(256) edge_kernel(const float* __restrict__ edge)
{
    const int i0 = blockIdx.x * 2;
    const int b  = blockIdx.y;
    const int t  = threadIdx.x;

    __shared__ float sm[SS];                   // 0.0 or +inf
    for (int k = t; k < SS; k += 256) sm[k] = g_maskf[b * SS + k];
    __syncthreads();

    const float4* __restrict__ row0 =
        (const float4*)(edge + ((size_t)(b * SS + i0)) * (size_t)ROWF);
    const float4* __restrict__ row1 = row0 + ROWF4;

    const float INF = __int_as_float(0x7f800000);
    float sumA0 = 0.0f, sumA1 = 0.0f, sumB0 = 0.0f, sumB1 = 0.0f;
    float mnA = INF, mnB = INF;
    #pragma unroll
    for (int it = 0; it < ROWF4 / 256; it++) {
        const int k = t + it * 256;
        float4 va = __ldcs(row0 + k);
        float4 vb = __ldcs(row1 + k);
        if (it & 1) { sumA1 += (va.x + va.y) + (va.z + va.w);
                      sumB1 += (vb.x + vb.y) + (vb.z + vb.w); }
        else        { sumA0 += (va.x + va.y) + (va.z + va.w);
                      sumB0 += (vb.x + vb.y) + (vb.z + vb.w); }
        if ((k & 3) == 0) {                    // channel 0 of edge feature j
            const float mf = sm[k >> 2];
            mnA = fminf(mnA, va.x + mf);
            mnB = fminf(mnB, vb.x + mf);
        }
    }
    float sumA = sumA0 + sumA1;
    float sumB = sumB0 + sumB1;

    // warp reduce (4 values)
    #pragma unroll
    for (int o = 16; o; o >>= 1) {
        sumA += __shfl_xor_sync(0xFFFFFFFFu, sumA, o);
        sumB += __shfl_xor_sync(0xFFFFFFFFu, sumB, o);
        mnA   = fminf(mnA, __shfl_xor_sync(0xFFFFFFFFu, mnA, o));
        mnB   = fminf(mnB, __shfl_xor_sync(0xFFFFFFFFu, mnB, o));
    }
    __shared__ float sredA[8], sredB[8], smnA[8], smnB[8];
    const int wid = t >> 5, lid = t & 31;
    if (lid == 0) { sredA[wid] = sumA; sredB[wid] = sumB; smnA[wid] = mnA; smnB[wid] = mnB; }
    __syncthreads();
    if (t == 0) {
        float SA = 0.0f, SB = 0.0f, MA = INF, MB = INF;
        #pragma unroll
        for (int k = 0; k < 8; k++) {
            SA += sredA[k]; SB += sredB[k];
            MA = fminf(MA, smnA[k]); MB = fminf(MB, smnB[k]);
        }
        g_edge_sum[b * SS + i0]     = SA;
        g_edge_sum[b * SS + i0 + 1] = SB;
        g_dist[b * SS + i0]         = MA;
        g_dist[b * SS + i0 + 1]     = MB;
    }
}

// ============================================================================
// Kernel 3: importance + fused finalize.
// One warp per row (1536 blocks). The LAST block to arrive (device counter)
// runs the per-batch finalize: 8 warps x 2 batches, fixed-order reductions.
// ============================================================================
__global__ void __launch_bounds__(256) imp_kernel(const float* __restrict__ node,
                                                  const float* __restrict__ seqmask,
                                                  const float* __restrict__ We1,
                                                  const float* __restrict__ be1,
                                                  float* __restrict__ out, int out_size)
{
    __shared__ float swnc[HID], sv[64], sw1[64], sb1[64];
    __shared__ int s_last;
    const int t = threadIdx.x;
    if (t < HID) swnc[t] = g_wnc[t];
    if (t < 64) { sv[t] = g_v[t]; sw1[t] = We1[t]; sb1[t] = be1[t]; }
    __syncthreads();

    const int w = t >> 5, l = t & 31;
    const int row = blockIdx.x * 8 + w;   // BSN/8 blocks

    const float4* nr = (const float4*)(node + (size_t)row * HID);
    const float4 nv = __ldg(nr + l);      // 32 lanes x float4 = 128 elems
    float acc = nv.x * swnc[l * 4 + 0] + nv.y * swnc[l * 4 + 1]
              + nv.z * swnc[l * 4 + 2] + nv.w * swnc[l * 4 + 3];

    const float es = g_edge_sum[row] * (1.0f / (float)ROWF);
    const float h0 = fmaxf(es * sw1[l]      + sb1[l],      0.0f);
    const float h1 = fmaxf(es * sw1[l + 32] + sb1[l + 32], 0.0f);
    acc += h0 * sv[l] + h1 * sv[l + 32];

    #pragma unroll
    for (int o = 16; o; o >>= 1) acc += __shfl_xor_sync(0xFFFFFFFFu, acc, o);

    if (l == 0) {
        const float logit = acc + g_C[0];
        const float imp = 1.0f / (1.0f + expf(-logit));   // accurate exp
        g_imp[row] = imp * seqmask[row];
    }

    // ---- arrival: last block finalizes ----
    __threadfence();                      // release g_imp writes
    __syncthreads();
    if (t == 0) {
        unsigned int prev = atomicAdd(&g_arrive, 1u);
        s_last = (prev == (unsigned int)(IMP_BLOCKS - 1)) ? 1 : 0;
    }
    __syncthreads();
    if (!s_last) return;
    __threadfence();                      // acquire: all g_imp visible

    // 8 warps; warp w handles batches w and w+8. 24 elems per lane per batch.
    #pragma unroll
    for (int pass = 0; pass < 2; pass++) {
        const int b = w + pass * 8;
        const int base = b * SS;

        // mean of imp (deterministic fixed lane order)
        float s = 0.0f;
        #pragma unroll
        for (int it = 0; it < SS / 32; it++) s += g_imp[base + l + it * 32];
        #pragma unroll
        for (int o = 16; o; o >>= 1) s += __shfl_xor_sync(0xFFFFFFFFu, s, o);
        const float mean = s * (1.0f / (float)SS);

        int cnt = 0, anyp = 0;
        #pragma unroll
        for (int it = 0; it < SS / 32; it++) {
            const int idx = base + l + it * 32;
            const bool p = g_mask[idx] != 0;
            const float d = g_dist[idx];
            const bool core  = d < 6.0f;
            const bool shell = (d >= 6.0f) && (d < 10.0f) && (g_imp[idx] > mean);
            cnt += (p | core | shell) ? 1 : 0;
            anyp |= p ? 1 : 0;
        }
        #pragma unroll
        for (int o = 16; o; o >>= 1) {
            cnt  += __shfl_xor_sync(0xFFFFFFFFu, cnt, o);
            anyp |= __shfl_xor_sync(0xFFFFFFFFu, anyp, o);
        }

        if (l == 0) {
            float chunk;
            if (anyp) {
                int ml = cnt; if (ml > 256) ml = 256;              // merged_len clamp
                chunk = fminf(fmaxf((float)ml, 64.0f), 256.0f);    // clamp(adj=64, 256)
            } else {
                chunk = fminf(fmaxf(64.0f * mean, 32.0f), 128.0f); // clip(64*imp, 32, 128)
            }
            out[b] = chunk;
        }
    }
    // pad remaining outputs (MAX_SEQ_LEN)
    for (int k = BB + t; k < out_size; k += 256) out[k] = 256.0f;
}

// ============================================================================
extern "C" void kernel_launch(void* const* d_in, const int* in_sizes, int n_in,
                              void* d_out, int out_size)
{
    const float* node    = (const float*)d_in[0];   // [16,768,128]
    const float* edge    = (const float*)d_in[1];   // [16,768,768,16]
    const float* seqmask = (const float*)d_in[2];   // [16,768]
    const void*  pocket  = d_in[3];                 // [16,768] dtype detected at runtime
    const float* W_node  = (const float*)d_in[4];
    const float* b_node  = (const float*)d_in[5];
    const float* W_e1    = (const float*)d_in[6];
    const float* b_e1    = (const float*)d_in[7];
    const float* W_e2    = (const float*)d_in[8];
    const float* b_e2    = (const float*)d_in[9];
    const float* W_imp   = (const float*)d_in[10];
    const float* b_imp   = (const float*)d_in[11];
    float* out = (float*)d_out;

    prep_kernel<<<1, 256>>>(pocket, W_node, b_node, W_e2, b_e2, W_imp, b_imp);

    dim3 eg(SS / 2, BB);
    edge_kernel<<<eg, 256>>>(edge);

    imp_kernel<<<IMP_BLOCKS, 256>>>(node, seqmask, W_e1, b_e1, out, out_size);
}

// round 4
// speedup vs baseline: 1.0220x; 1.0220x over previous
#include <cuda_runtime.h>
#include <cuda_bf16.h>
#include <cstdint>

// Problem shape (fixed for this problem id)
#define BB   16
#define SS   768
#define DE   16
#define HID  128
#define BSN  (BB*SS)          // 12288 rows
#define ROWF (SS*DE)          // 12288 floats per (b,i) row
#define ROWF4 (ROWF/4)        // 3072 float4 per row
#define IMP_BLOCKS (BSN/8)    // 1536 blocks in imp kernel

// ---- scratch (no allocations allowed) ----
__device__ float g_edge_sum[BSN];
__device__ float g_dist[BSN];
__device__ float g_imp[BSN];
__device__ float g_wnc[HID];
__device__ float g_v[64];
__device__ float g_C[1];
__device__ float g_maskf[BSN];           // 0.0 = pocket, +inf = not
__device__ unsigned char g_mask[BSN];
__device__ unsigned int g_arrive;

// ============================================================================
// Kernel 1: prep — detect pocket_mask dtype, canonicalize, fold weights,
// reset arrival counter. 512 threads; loops unrolled so loads batch (MLP>>1).
// ============================================================================
__global__ void __launch_bounds__(512) prep_kernel(
                            const void* __restrict__ pocket_raw,
                            const float* __restrict__ W_node,
                            const float* __restrict__ b_node,
                            const float* __restrict__ W_e2,
                            const float* __restrict__ b_e2,
                            const float* __restrict__ W_imp,
                            const float* __restrict__ b_imp)
{
    __shared__ int s_fone, s_other;
    const int t = threadIdx.x;
    if (t == 0) { s_fone = 0; s_other = 0; g_arrive = 0u; }
    __syncthreads();

    // ---- dtype scan: 3072 words, 512 threads, 6 unrolled independent loads
    {
        const unsigned int* w = (const unsigned int*)pocket_raw;
        unsigned int x[6];
        #pragma unroll
        for (int u = 0; u < 6; u++) x[u] = w[t + u * 512];
        int lf = 0, lo = 0;
        #pragma unroll
        for (int u = 0; u < 6; u++) {
            if (x[u] == 0x3F800000u) lf++;
            else if (x[u] != 0u && x[u] != 1u) lo++;
        }
        if (lf) atomicAdd(&s_fone, lf);
        if (lo) atomicAdd(&s_other, lo);
    }
    __syncthreads();
    // mode: 0=float32 (saw 1.0f words), 2=bool/u8 (packed-byte patterns), 1=int32
    const int mode = (s_fone > 0) ? 0 : ((s_other > 0) ? 2 : 1);

    // ---- canonicalize: branch hoisted, 24 unrolled loads per thread
    const float INF = __int_as_float(0x7f800000);
    if (mode == 0) {
        const float* p = (const float*)pocket_raw;
        #pragma unroll
        for (int u = 0; u < BSN / 512; u++) {
            const int idx = t + u * 512;
            const bool m = p[idx] != 0.0f;
            g_mask[idx] = m ? 1 : 0;
            g_maskf[idx] = m ? 0.0f : INF;
        }
    } else if (mode == 1) {
        const int* p = (const int*)pocket_raw;
        #pragma unroll
        for (int u = 0; u < BSN / 512; u++) {
            const int idx = t + u * 512;
            const bool m = p[idx] != 0;
            g_mask[idx] = m ? 1 : 0;
            g_maskf[idx] = m ? 0.0f : INF;
        }
    } else {
        const unsigned char* p = (const unsigned char*)pocket_raw;
        #pragma unroll
        for (int u = 0; u < BSN / 512; u++) {
            const int idx = t + u * 512;
            const bool m = p[idx] != 0;
            g_mask[idx] = m ? 1 : 0;
            g_maskf[idx] = m ? 0.0f : INF;
        }
    }

    // ---- weight folding (per-thread contiguous 128B rows; loads batch)
    if (t < HID) {
        float s = 0.0f;
        #pragma unroll
        for (int k = 0; k < 32; k++) s += W_node[t * 32 + k] * W_imp[k];
        g_wnc[t] = s;
    }
    if (t < 64) {
        float s = 0.0f;
        #pragma unroll
        for (int k = 0; k < 32; k++) s += W_e2[t * 32 + k] * W_imp[32 + k];
        g_v[t] = s;
    }
    if (t == 0) {
        float c = b_imp[0];
        #pragma unroll
        for (int k = 0; k < 32; k++) c += b_node[k] * W_imp[k];
        #pragma unroll
        for (int k = 0; k < 32; k++) c += b_e2[k] * W_imp[32 + k];
        g_C[0] = c;
    }
}

// ============================================================================
// Kernel 2: edge pass — the 604 MB streaming pass (R2 structure: 1 row/block).
// Streaming loads (__ldcs): each byte touched exactly once.
// Channel-0 element: float4 index k with k%4==0, component .x, j = k>>2.
// Min via additive-inf mask: cand = v.x + maskf[j]  (FADD, no select).
// ============================================================================
__global__ void __launch_bounds__(256) edge_kernel(const float* __restrict__ edge)
{
    const int i = blockIdx.x;
    const int b = blockIdx.y;
    const int t = threadIdx.x;

    __shared__ float sm[SS];                   // 0.0 or +inf
    for (int k = t; k < SS; k += 256) sm[k] = g_maskf[b * SS + k];
    __syncthreads();

    const float4* __restrict__ row =
        (const float4*)(edge + ((size_t)(b * SS + i)) * (size_t)ROWF);

    const float INF = __int_as_float(0x7f800000);
    float sum0 = 0.0f, sum1 = 0.0f;
    float mn = INF;
    #pragma unroll
    for (int it = 0; it < ROWF4 / 256; it++) {
        const int k = t + it * 256;
        float4 v = __ldcs(row + k);
        if (it & 1) sum1 += (v.x + v.y) + (v.z + v.w);
        else        sum0 += (v.x + v.y) + (v.z + v.w);
        if ((k & 3) == 0) {                 // channel 0 of edge feature j
            mn = fminf(mn, v.x + sm[k >> 2]);
        }
    }
    float sum = sum0 + sum1;

    // warp reduce
    #pragma unroll
    for (int o = 16; o; o >>= 1) {
        sum += __shfl_xor_sync(0xFFFFFFFFu, sum, o);
        mn   = fminf(mn, __shfl_xor_sync(0xFFFFFFFFu, mn, o));
    }
    __shared__ float ssum[8], smn[8];
    const int wid = t >> 5, lid = t & 31;
    if (lid == 0) { ssum[wid] = sum; smn[wid] = mn; }
    __syncthreads();
    if (t == 0) {
        float S = 0.0f, M = INF;
        #pragma unroll
        for (int k = 0; k < 8; k++) { S += ssum[k]; M = fminf(M, smn[k]); }
        g_edge_sum[b * SS + i] = S;
        g_dist[b * SS + i]     = M;
    }
}

// ============================================================================
// Kernel 3: importance + fused finalize.
// One warp per row (1536 blocks). The LAST block to arrive (device counter)
// runs the per-batch finalize: 8 warps x 2 batches, fixed-order reductions.
// ============================================================================
__global__ void __launch_bounds__(256) imp_kernel(const float* __restrict__ node,
                                                  const float* __restrict__ seqmask,
                                                  const float* __restrict__ We1,
                                                  const float* __restrict__ be1,
                                                  float* __restrict__ out, int out_size)
{
    __shared__ float swnc[HID], sv[64], sw1[64], sb1[64];
    __shared__ int s_last;
    const int t = threadIdx.x;
    if (t < HID) swnc[t] = g_wnc[t];
    if (t < 64) { sv[t] = g_v[t]; sw1[t] = We1[t]; sb1[t] = be1[t]; }
    __syncthreads();

    const int w = t >> 5, l = t & 31;
    const int row = blockIdx.x * 8 + w;   // BSN/8 blocks

    const float4* nr = (const float4*)(node + (size_t)row * HID);
    const float4 nv = __ldg(nr + l);      // 32 lanes x float4 = 128 elems
    float acc = nv.x * swnc[l * 4 + 0] + nv.y * swnc[l * 4 + 1]
              + nv.z * swnc[l * 4 + 2] + nv.w * swnc[l * 4 + 3];

    const float es = g_edge_sum[row] * (1.0f / (float)ROWF);
    const float h0 = fmaxf(es * sw1[l]      + sb1[l],      0.0f);
    const float h1 = fmaxf(es * sw1[l + 32] + sb1[l + 32], 0.0f);
    acc += h0 * sv[l] + h1 * sv[l + 32];

    #pragma unroll
    for (int o = 16; o; o >>= 1) acc += __shfl_xor_sync(0xFFFFFFFFu, acc, o);

    if (l == 0) {
        const float logit = acc + g_C[0];
        const float imp = 1.0f / (1.0f + expf(-logit));   // accurate exp
        g_imp[row] = imp * seqmask[row];
    }

    // ---- arrival: last block finalizes ----
    __threadfence();                      // release g_imp writes
    __syncthreads();
    if (t == 0) {
        unsigned int prev = atomicAdd(&g_arrive, 1u);
        s_last = (prev == (unsigned int)(IMP_BLOCKS - 1)) ? 1 : 0;
    }
    __syncthreads();
    if (!s_last) return;
    __threadfence();                      // acquire: all g_imp visible

    // 8 warps; warp w handles batches w and w+8. 24 elems per lane per batch.
    #pragma unroll
    for (int pass = 0; pass < 2; pass++) {
        const int b = w + pass * 8;
        const int base = b * SS;

        // mean of imp (deterministic fixed lane order)
        float s = 0.0f;
        #pragma unroll
        for (int it = 0; it < SS / 32; it++) s += g_imp[base + l + it * 32];
        #pragma unroll
        for (int o = 16; o; o >>= 1) s += __shfl_xor_sync(0xFFFFFFFFu, s, o);
        const float mean = s * (1.0f / (float)SS);

        int cnt = 0, anyp = 0;
        #pragma unroll
        for (int it = 0; it < SS / 32; it++) {
            const int idx = base + l + it * 32;
            const bool p = g_mask[idx] != 0;
            const float d = g_dist[idx];
            const bool core  = d < 6.0f;
            const bool shell = (d >= 6.0f) && (d < 10.0f) && (g_imp[idx] > mean);
            cnt += (p | core | shell) ? 1 : 0;
            anyp |= p ? 1 : 0;
        }
        #pragma unroll
        for (int o = 16; o; o >>= 1) {
            cnt  += __shfl_xor_sync(0xFFFFFFFFu, cnt, o);
            anyp |= __shfl_xor_sync(0xFFFFFFFFu, anyp, o);
        }

        if (l == 0) {
            float chunk;
            if (anyp) {
                int ml = cnt; if (ml > 256) ml = 256;              // merged_len clamp
                chunk = fminf(fmaxf((float)ml, 64.0f), 256.0f);    // clamp(adj=64, 256)
            } else {
                chunk = fminf(fmaxf(64.0f * mean, 32.0f), 128.0f); // clip(64*imp, 32, 128)
            }
            out[b] = chunk;
        }
    }
    // pad remaining outputs (MAX_SEQ_LEN)
    for (int k = BB + t; k < out_size; k += 256) out[k] = 256.0f;
}

// ============================================================================
extern "C" void kernel_launch(void* const* d_in, const int* in_sizes, int n_in,
                              void* d_out, int out_size)
{
    const float* node    = (const float*)d_in[0];   // [16,768,128]
    const float* edge    = (const float*)d_in[1];   // [16,768,768,16]
    const float* seqmask = (const float*)d_in[2];   // [16,768]
    const void*  pocket  = d_in[3];                 // [16,768] dtype detected at runtime
    const float* W_node  = (const float*)d_in[4];
    const float* b_node  = (const float*)d_in[5];
    const float* W_e1    = (const float*)d_in[6];
    const float* b_e1    = (const float*)d_in[7];
    const float* W_e2    = (const float*)d_in[8];
    const float* b_e2    = (const float*)d_in[9];
    const float* W_imp   = (const float*)d_in[10];
    const float* b_imp   = (const float*)d_in[11];
    float* out = (float*)d_out;

    prep_kernel<<<1, 512>>>(pocket, W_node, b_node, W_e2, b_e2, W_imp, b_imp);

    dim3 eg(SS, BB);
    edge_kernel<<<eg, 256>>>(edge);

    imp_kernel<<<IMP_BLOCKS, 256>>>(node, seqmask, W_e1, b_e1, out, out_size);
}

// round 5
// speedup vs baseline: 1.1454x; 1.1208x over previous
#include <cuda_runtime.h>
#include <cuda_bf16.h>
#include <cstdint>

// Problem shape (fixed for this problem id)
#define BB   16
#define SS   768
#define DE   16
#define HID  128
#define BSN  (BB*SS)          // 12288 rows
#define ROWF (SS*DE)          // 12288 floats per (b,i) row
#define ROWF4 (ROWF/4)        // 3072 float4 per row

// ---- scratch (no allocations allowed) ----
__device__ float g_edge_sum[BSN];
__device__ float g_dist[BSN];
__device__ float g_imp[BSN];
__device__ float g_wnc[HID];
__device__ float g_v[64];
__device__ float g_C[1];
__device__ unsigned char g_mask[BSN];

// ============================================================================
// Kernel 1: prep — detect pocket_mask dtype, canonicalize, fold weights.
// 512 threads; mode branch hoisted; loops unrolled so loads batch (high MLP).
// ============================================================================
__global__ void __launch_bounds__(512) prep_kernel(
                            const void* __restrict__ pocket_raw,
                            const float* __restrict__ W_node,
                            const float* __restrict__ b_node,
                            const float* __restrict__ W_e2,
                            const float* __restrict__ b_e2,
                            const float* __restrict__ W_imp,
                            const float* __restrict__ b_imp)
{
    __shared__ int s_fone, s_other;
    const int t = threadIdx.x;
    if (t == 0) { s_fone = 0; s_other = 0; }
    __syncthreads();

    // ---- dtype scan: 3072 words, 512 threads, 6 unrolled independent loads
    {
        const unsigned int* w = (const unsigned int*)pocket_raw;
        unsigned int x[6];
        #pragma unroll
        for (int u = 0; u < 6; u++) x[u] = w[t + u * 512];
        int lf = 0, lo = 0;
        #pragma unroll
        for (int u = 0; u < 6; u++) {
            if (x[u] == 0x3F800000u) lf++;
            else if (x[u] != 0u && x[u] != 1u) lo++;
        }
        if (lf) atomicAdd(&s_fone, lf);
        if (lo) atomicAdd(&s_other, lo);
    }
    __syncthreads();
    // mode: 0=float32 (saw 1.0f words), 2=bool/u8 (packed-byte patterns), 1=int32
    const int mode = (s_fone > 0) ? 0 : ((s_other > 0) ? 2 : 1);

    // ---- canonicalize: branch hoisted, 24 unrolled loads per thread
    if (mode == 0) {
        const float* p = (const float*)pocket_raw;
        #pragma unroll
        for (int u = 0; u < BSN / 512; u++) {
            const int idx = t + u * 512;
            g_mask[idx] = (p[idx] != 0.0f) ? 1 : 0;
        }
    } else if (mode == 1) {
        const int* p = (const int*)pocket_raw;
        #pragma unroll
        for (int u = 0; u < BSN / 512; u++) {
            const int idx = t + u * 512;
            g_mask[idx] = (p[idx] != 0) ? 1 : 0;
        }
    } else {
        const unsigned char* p = (const unsigned char*)pocket_raw;
        #pragma unroll
        for (int u = 0; u < BSN / 512; u++) {
            const int idx = t + u * 512;
            g_mask[idx] = (p[idx] != 0) ? 1 : 0;
        }
    }

    // ---- weight folding (per-thread contiguous 128B rows; loads batch)
    if (t < HID) {
        float s = 0.0f;
        #pragma unroll
        for (int k = 0; k < 32; k++) s += W_node[t * 32 + k] * W_imp[k];
        g_wnc[t] = s;
    }
    if (t < 64) {
        float s = 0.0f;
        #pragma unroll
        for (int k = 0; k < 32; k++) s += W_e2[t * 32 + k] * W_imp[32 + k];
        g_v[t] = s;
    }
    if (t == 0) {
        float c = b_imp[0];
        #pragma unroll
        for (int k = 0; k < 32; k++) c += b_node[k] * W_imp[k];
        #pragma unroll
        for (int k = 0; k < 32; k++) c += b_e2[k] * W_imp[32 + k];
        g_C[0] = c;
    }
}

// ============================================================================
// Kernel 2: edge pass — the 604 MB streaming pass (R2 exact).
// One block per (b,i) row: fused (sum over S*De) + (masked min over channel 0).
// Streaming loads (__ldcs): each byte is touched exactly once.
// Channel-0 element sits at float4 index k with k%4==0, component .x, j=k>>2.
// ============================================================================
__global__ void __launch_bounds__(256) edge_kernel(const float* __restrict__ edge)
{
    const int i = blockIdx.x;
    const int b = blockIdx.y;
    const int t = threadIdx.x;

    __shared__ unsigned char sm[SS];
    for (int k = t; k < SS; k += 256) sm[k] = g_mask[b * SS + k];
    __syncthreads();

    const float4* __restrict__ row =
        (const float4*)(edge + ((size_t)(b * SS + i)) * (size_t)ROWF);

    const float INF = __int_as_float(0x7f800000);
    float sum0 = 0.0f, sum1 = 0.0f;
    float mn = INF;
    #pragma unroll
    for (int it = 0; it < ROWF4 / 256; it++) {
        const int k = t + it * 256;
        float4 v = __ldcs(row + k);
        if (it & 1) sum1 += (v.x + v.y) + (v.z + v.w);
        else        sum0 += (v.x + v.y) + (v.z + v.w);
        if ((k & 3) == 0) {                 // channel 0 of edge feature j
            const int j = k >> 2;
            const float cand = sm[j] ? v.x : INF;   // select, no branch
            mn = fminf(mn, cand);
        }
    }
    float sum = sum0 + sum1;

    // warp reduce
    #pragma unroll
    for (int o = 16; o; o >>= 1) {
        sum += __shfl_xor_sync(0xFFFFFFFFu, sum, o);
        mn   = fminf(mn, __shfl_xor_sync(0xFFFFFFFFu, mn, o));
    }
    __shared__ float ssum[8], smn[8];
    const int wid = t >> 5, lid = t & 31;
    if (lid == 0) { ssum[wid] = sum; smn[wid] = mn; }
    __syncthreads();
    if (t == 0) {
        float S = 0.0f, M = INF;
        #pragma unroll
        for (int k = 0; k < 8; k++) { S += ssum[k]; M = fminf(M, smn[k]); }
        g_edge_sum[b * SS + i] = S;
        g_dist[b * SS + i]     = M;
    }
}

// ============================================================================
// Kernel 3: importance — one warp per row (1536 blocks, full chip). R2 exact.
// ============================================================================
__global__ void __launch_bounds__(256) imp_kernel(const float* __restrict__ node,
                                                  const float* __restrict__ seqmask,
                                                  const float* __restrict__ We1,
                                                  const float* __restrict__ be1)
{
    __shared__ float swnc[HID], sv[64], sw1[64], sb1[64];
    const int t = threadIdx.x;
    if (t < HID) swnc[t] = g_wnc[t];
    if (t < 64) { sv[t] = g_v[t]; sw1[t] = We1[t]; sb1[t] = be1[t]; }
    __syncthreads();

    const int w = t >> 5, l = t & 31;
    const int row = blockIdx.x * 8 + w;   // BSN/8 blocks

    const float4* nr = (const float4*)(node + (size_t)row * HID);
    const float4 nv = __ldg(nr + l);      // 32 lanes x float4 = 128 elems
    float acc = nv.x * swnc[l * 4 + 0] + nv.y * swnc[l * 4 + 1]
              + nv.z * swnc[l * 4 + 2] + nv.w * swnc[l * 4 + 3];

    const float es = g_edge_sum[row] * (1.0f / (float)ROWF);
    const float h0 = fmaxf(es * sw1[l]      + sb1[l],      0.0f);
    const float h1 = fmaxf(es * sw1[l + 32] + sb1[l + 32], 0.0f);
    acc += h0 * sv[l] + h1 * sv[l + 32];

    #pragma unroll
    for (int o = 16; o; o >>= 1) acc += __shfl_xor_sync(0xFFFFFFFFu, acc, o);

    if (l == 0) {
        const float logit = acc + g_C[0];
        const float imp = 1.0f / (1.0f + expf(-logit));   // accurate exp
        g_imp[row] = imp * seqmask[row];
    }
}

// ============================================================================
// Kernel 4: finalize — one block per batch; shuffle reductions. R2 exact.
// ============================================================================
__global__ void __launch_bounds__(256) final_kernel(float* __restrict__ out, int out_size)
{
    const int b = blockIdx.x, t = threadIdx.x;
    const int w = t >> 5, l = t & 31;
    __shared__ float wred[8];
    __shared__ float s_mean;
    __shared__ int   wcnt[8], wany[8];

    // ---- mean of imp over the batch (deterministic fixed order) ----
    float s = 0.0f;
    #pragma unroll
    for (int it = 0; it < SS / 256; it++) s += g_imp[b * SS + t + it * 256];
    #pragma unroll
    for (int o = 16; o; o >>= 1) s += __shfl_xor_sync(0xFFFFFFFFu, s, o);
    if (l == 0) wred[w] = s;
    __syncthreads();
    if (t == 0) {
        float S = 0.0f;
        #pragma unroll
        for (int k = 0; k < 8; k++) S += wred[k];
        s_mean = S * (1.0f / (float)SS);
    }
    __syncthreads();
    const float mean = s_mean;

    // ---- merged count + any(pocket) ----
    int cnt = 0, anyp = 0;
    #pragma unroll
    for (int it = 0; it < SS / 256; it++) {
        const int idx = b * SS + t + it * 256;
        const bool p = g_mask[idx] != 0;
        const float d = g_dist[idx];
        const bool core  = d < 6.0f;
        const bool shell = (d >= 6.0f) && (d < 10.0f) && (g_imp[idx] > mean);
        cnt += (p | core | shell) ? 1 : 0;
        anyp |= p ? 1 : 0;
    }
    #pragma unroll
    for (int o = 16; o; o >>= 1) {
        cnt  += __shfl_xor_sync(0xFFFFFFFFu, cnt, o);
        anyp |= __shfl_xor_sync(0xFFFFFFFFu, anyp, o);
    }
    if (l == 0) { wcnt[w] = cnt; wany[w] = anyp; }
    __syncthreads();

    if (t == 0) {
        int C = 0, A = 0;
        #pragma unroll
        for (int k = 0; k < 8; k++) { C += wcnt[k]; A |= wany[k]; }
        float chunk;
        if (A) {
            int ml = C; if (ml > 256) ml = 256;                // merged_len clamp
            chunk = fminf(fmaxf((float)ml, 64.0f), 256.0f);    // clamp(adj=64, 256)
        } else {
            chunk = fminf(fmaxf(64.0f * mean, 32.0f), 128.0f); // clip(64*imp, 32, 128)
        }
        out[b] = chunk;
    }
    // pad remaining outputs (MAX_SEQ_LEN) in parallel from block 0
    if (b == 0) {
        for (int k = BB + t; k < out_size; k += 256) out[k] = 256.0f;
    }
}

// ============================================================================
extern "C" void kernel_launch(void* const* d_in, const int* in_sizes, int n_in,
                              void* d_out, int out_size)
{
    const float* node    = (const float*)d_in[0];   // [16,768,128]
    const float* edge    = (const float*)d_in[1];   // [16,768,768,16]
    const float* seqmask = (const float*)d_in[2];   // [16,768]
    const void*  pocket  = d_in[3];                 // [16,768] dtype detected at runtime
    const float* W_node  = (const float*)d_in[4];
    const float* b_node  = (const float*)d_in[5];
    const float* W_e1    = (const float*)d_in[6];
    const float* b_e1    = (const float*)d_in[7];
    const float* W_e2    = (const float*)d_in[8];
    const float* b_e2    = (const float*)d_in[9];
    const float* W_imp   = (const float*)d_in[10];
    const float* b_imp   = (const float*)d_in[11];
    float* out = (float*)d_out;

    prep_kernel<<<1, 512>>>(pocket, W_node, b_node, W_e2, b_e2, W_imp, b_imp);

    dim3 eg(SS, BB);
    edge_kernel<<<eg, 256>>>(edge);

    imp_kernel<<<BSN / 8, 256>>>(node, seqmask, W_e1, b_e1);

    final_kernel<<<BB, 256>>>(out, out_size);
}